// round 7
// baseline (speedup 1.0000x reference)
#include <cuda_runtime.h>
#include <cuda_bf16.h>
#include <cstdint>
#include <math.h>

#define BDIM 4096
#define DDIM 1024
#define HDIM 1024

// ---------------------------------------------------------------------------
// Device scratch
// ---------------------------------------------------------------------------
__device__ float g_scratch[6ull * BDIM * HDIM];                 // 6 GEMM outputs fp32
__device__ __align__(16) __nv_bfloat16 g_ahi[2ull * BDIM * DDIM];  // act hi  [inp, ph]
__device__ __align__(16) __nv_bfloat16 g_alo[2ull * BDIM * DDIM];  // act lo
__device__ __align__(16) __nv_bfloat16 g_wthi[6ull * HDIM * DDIM]; // W^T hi (K-major)
__device__ __align__(16) __nv_bfloat16 g_wtlo[6ull * HDIM * DDIM]; // W^T lo

// ---------------------------------------------------------------------------
// PTX helpers (sm_80-compatible only)
// ---------------------------------------------------------------------------
__device__ __forceinline__ uint32_t smem_u32(const void* p) {
    uint32_t a;
    asm("{ .reg .u64 t; cvta.to.shared.u64 t, %1; cvt.u32.u64 %0, t; }" : "=r"(a) : "l"(p));
    return a;
}
#define CP16(s, g) \
    asm volatile("cp.async.cg.shared.global [%0], [%1], 16;" :: "r"(s), "l"(g))
#define CP_COMMIT() asm volatile("cp.async.commit_group;" ::: "memory")
#define CP_WAIT(n)  asm volatile("cp.async.wait_group %0;" :: "n"(n) : "memory")

__device__ __forceinline__ void ldm_x4(uint32_t* r, uint32_t addr) {
    asm volatile("ldmatrix.sync.aligned.m8n8.x4.shared.b16 {%0,%1,%2,%3}, [%4];"
                 : "=r"(r[0]), "=r"(r[1]), "=r"(r[2]), "=r"(r[3]) : "r"(addr));
}
__device__ __forceinline__ void mma_bf16(float* d, const uint32_t* a,
                                         uint32_t b0, uint32_t b1) {
    asm volatile(
        "mma.sync.aligned.m16n8k16.row.col.f32.bf16.bf16.f32 "
        "{%0,%1,%2,%3}, {%4,%5,%6,%7}, {%8,%9}, {%0,%1,%2,%3};"
        : "+f"(d[0]), "+f"(d[1]), "+f"(d[2]), "+f"(d[3])
        : "r"(a[0]), "r"(a[1]), "r"(a[2]), "r"(a[3]), "r"(b0), "r"(b1));
}
// SW32 swizzle for 32-byte rows: bit[4] ^= bit[7]. Conflict-free for
// ldmatrix 8-row phases and the 16B cp.async stores (verified bank map).
__device__ __forceinline__ uint32_t swz32(uint32_t off) {
    return off ^ ((off >> 3) & 0x10);
}

// ---------------------------------------------------------------------------
// Prep: split activations into bf16 hi/lo
// ---------------------------------------------------------------------------
__global__ __launch_bounds__(256)
void asplit(const float* __restrict__ inp, const float* __restrict__ ph)
{
    const int t = blockIdx.y;
    const float* src = t ? ph : inp;
    size_t base = ((size_t)blockIdx.x * 256 + threadIdx.x) * 4;
    float4 v = *(const float4*)&src[base];
    __nv_bfloat16 h[4], l[4];
    float vv[4] = {v.x, v.y, v.z, v.w};
    #pragma unroll
    for (int i = 0; i < 4; i++) {
        h[i] = __float2bfloat16(vv[i]);
        l[i] = __float2bfloat16(vv[i] - __bfloat162float(h[i]));
    }
    size_t off = (size_t)t * BDIM * DDIM + base;
    *(uint2*)&g_ahi[off] = *(uint2*)h;
    *(uint2*)&g_alo[off] = *(uint2*)l;
}

// ---------------------------------------------------------------------------
// Prep: transpose + split weights into bf16 hi/lo, K-major [N][K]
// ---------------------------------------------------------------------------
__global__ __launch_bounds__(256)
void wsplit(const float* __restrict__ w0, const float* __restrict__ w1,
            const float* __restrict__ w2, const float* __restrict__ w3,
            const float* __restrict__ w4, const float* __restrict__ w5)
{
    __shared__ float t[32][33];
    const int z = blockIdx.z;
    const float* W;
    switch (z) { case 0: W = w0; break; case 1: W = w1; break; case 2: W = w2; break;
                 case 3: W = w3; break; case 4: W = w4; break; default: W = w5; }
    const int n0 = blockIdx.x * 32, k0 = blockIdx.y * 32;
    const int tx = threadIdx.x & 31, ty = threadIdx.x >> 5;   // 32 x 8
    #pragma unroll
    for (int i = 0; i < 4; i++)
        t[ty + 8 * i][tx] = W[(size_t)(k0 + ty + 8 * i) * HDIM + n0 + tx];
    __syncthreads();
    __nv_bfloat16* H = g_wthi + (size_t)z * HDIM * DDIM;
    __nv_bfloat16* L = g_wtlo + (size_t)z * HDIM * DDIM;
    #pragma unroll
    for (int i = 0; i < 4; i++) {
        float v = t[tx][ty + 8 * i];
        __nv_bfloat16 hi = __float2bfloat16(v);
        __nv_bfloat16 lo = __float2bfloat16(v - __bfloat162float(hi));
        size_t o = (size_t)(n0 + ty + 8 * i) * DDIM + k0 + tx;
        H[o] = hi; L[o] = lo;
    }
}

// ---------------------------------------------------------------------------
// mma.sync GEMM: C[z] (BxH) = A @ W[z], 3-term split-bf16, all terms per load.
// CTA tile 128x128, 8 warps (2M x 4N), warp tile 64x32.
// K chunks of 16; stage = {A_hi 4K | A_lo 4K | B_hi 4K | B_lo 4K} = 16KB.
// 3-stage cp.async ring in 48KB static smem, wait_group(2), 2 syncs/chunk.
// ---------------------------------------------------------------------------
#define STAGE_BYTES 16384
#define NCHUNK 64

__device__ __forceinline__ void load_chunk(uint32_t st, int c,
    const __nv_bfloat16* __restrict__ ahi, const __nv_bfloat16* __restrict__ alo,
    const __nv_bfloat16* __restrict__ bhi, const __nv_bfloat16* __restrict__ blo,
    int tid)
{
    const int k0 = c * 16;
    const int r = tid >> 1, kk = tid & 1;       // 256 threads: 128 rows x 2 chunks
    const uint32_t so = swz32((uint32_t)(r * 32 + kk * 16));
    const size_t go = (size_t)r * DDIM + k0 + kk * 8;
    CP16(st + so,         ahi + go);
    CP16(st + 4096 + so,  alo + go);
    CP16(st + 8192 + so,  bhi + go);
    CP16(st + 12288 + so, blo + go);
}

__global__ __launch_bounds__(256, 2)
void gemm_mma()
{
    __shared__ __align__(1024) char smem_buf[3][STAGE_BYTES];
    const uint32_t sb = smem_u32(smem_buf);
    const int tid = threadIdx.x, wid = tid >> 5, lid = tid & 31;
    const int wm = wid & 1;             // 0..1 -> M offset 64*wm
    const int wn = wid >> 1;            // 0..3 -> N offset 32*wn
    const int z = blockIdx.z;
    const int bm = blockIdx.y * 128;
    const int bn = blockIdx.x * 128;
    const int act = z & 1;

    const __nv_bfloat16* ahi = g_ahi + (size_t)act * BDIM * DDIM + (size_t)bm * DDIM;
    const __nv_bfloat16* alo = g_alo + (size_t)act * BDIM * DDIM + (size_t)bm * DDIM;
    const __nv_bfloat16* bhi = g_wthi + (size_t)z * HDIM * DDIM + (size_t)bn * DDIM;
    const __nv_bfloat16* blo = g_wtlo + (size_t)z * HDIM * DDIM + (size_t)bn * DDIM;

    float acc[4][4][4];                 // [M 16-tile][n8 tile][quad]
    #pragma unroll
    for (int i = 0; i < 4; i++)
        #pragma unroll
        for (int n = 0; n < 4; n++)
            #pragma unroll
            for (int q = 0; q < 4; q++) acc[i][n][q] = 0.f;

    load_chunk(sb, 0, ahi, alo, bhi, blo, tid);
    CP_COMMIT();
    load_chunk(sb + STAGE_BYTES, 1, ahi, alo, bhi, blo, tid);
    CP_COMMIT();

    const int lrow = lid & 15;
    const uint32_t lhalf = (uint32_t)((lid >> 4) * 16);
    int s = 0;

    for (int c = 0; c < NCHUNK; c++) {
        const uint32_t st = sb + (uint32_t)s * STAGE_BYTES;
        if (c + 2 < NCHUNK) {
            int s2 = s + 2; if (s2 >= 3) s2 -= 3;
            load_chunk(sb + (uint32_t)s2 * STAGE_BYTES, c + 2, ahi, alo, bhi, blo, tid);
            CP_COMMIT();
            CP_WAIT(2);
        } else if (c + 1 < NCHUNK) {
            CP_WAIT(1);
        } else {
            CP_WAIT(0);
        }
        __syncthreads();                // all threads' loads for stage s landed

        // A_hi (4 tiles, 64 rows) and B_hi (2 tiles, 32 N-rows)
        uint32_t ah[4][4], bh[2][4];
        #pragma unroll
        for (int i = 0; i < 4; i++) {
            uint32_t off = (uint32_t)((64 * wm + 16 * i + lrow) * 32) + lhalf;
            ldm_x4(ah[i], st + swz32(off));
        }
        #pragma unroll
        for (int j = 0; j < 2; j++) {
            uint32_t off = (uint32_t)((32 * wn + 16 * j + lrow) * 32) + lhalf;
            ldm_x4(bh[j], st + 8192 + swz32(off));
        }
        // term0: A_hi * B_hi
        #pragma unroll
        for (int i = 0; i < 4; i++)
            #pragma unroll
            for (int n = 0; n < 4; n++) {
                const int g = n >> 1, q = n & 1;
                mma_bf16(acc[i][n], ah[i], bh[g][q], bh[g][q + 2]);
            }
        // term1: A_hi * B_lo  (reuse ah; bl transient)
        {
            uint32_t bl[2][4];
            #pragma unroll
            for (int j = 0; j < 2; j++) {
                uint32_t off = (uint32_t)((32 * wn + 16 * j + lrow) * 32) + lhalf;
                ldm_x4(bl[j], st + 12288 + swz32(off));
            }
            #pragma unroll
            for (int i = 0; i < 4; i++)
                #pragma unroll
                for (int n = 0; n < 4; n++) {
                    const int g = n >> 1, q = n & 1;
                    mma_bf16(acc[i][n], ah[i], bl[g][q], bl[g][q + 2]);
                }
        }
        // term2: A_lo * B_hi  (reuse bh; al transient)
        {
            uint32_t al[4][4];
            #pragma unroll
            for (int i = 0; i < 4; i++) {
                uint32_t off = (uint32_t)((64 * wm + 16 * i + lrow) * 32) + lhalf;
                ldm_x4(al[i], st + 4096 + swz32(off));
            }
            #pragma unroll
            for (int i = 0; i < 4; i++)
                #pragma unroll
                for (int n = 0; n < 4; n++) {
                    const int g = n >> 1, q = n & 1;
                    mma_bf16(acc[i][n], al[i], bh[g][q], bh[g][q + 2]);
                }
        }
        __syncthreads();                // reads of stage s done before overwrite
        if (++s >= 3) s -= 3;
    }

    // Epilogue
    float* C = g_scratch + (size_t)z * BDIM * HDIM;
    const int erow = lid >> 2, ecol = (lid & 3) * 2;
    #pragma unroll
    for (int i = 0; i < 4; i++) {
        #pragma unroll
        for (int n = 0; n < 4; n++) {
            const int row = bm + 64 * wm + 16 * i + erow;
            const int col = bn + 32 * wn + 8 * n + ecol;
            float2 v0 = make_float2(acc[i][n][0], acc[i][n][1]);
            float2 v1 = make_float2(acc[i][n][2], acc[i][n][3]);
            *(float2*)&C[(size_t)row * HDIM + col]       = v0;
            *(float2*)&C[(size_t)(row + 8) * HDIM + col] = v1;
        }
    }
}

// ---------------------------------------------------------------------------
// Hyperbolic elementwise stage (fast-math transcendentals)
// ---------------------------------------------------------------------------
__device__ __forceinline__ float artanh_c(float v) {
    v = fminf(fmaxf(v, -1.f + 1e-5f), 1.f - 1e-5f);
    return 0.5f * __logf(__fdividef(1.f + v, 1.f - v));
}
__device__ __forceinline__ float tanh_fast(float x) {
    float e = __expf(-2.f * x);
    return __fdividef(1.f - e, 1.f + e);
}
__device__ __forceinline__ float sigmoid_fast(float x) {
    return __fdividef(1.f, 1.f + __expf(-x));
}
struct MA { float a, b, n2; };
__device__ __forceinline__ MA madd(float x2, float y2, float xy) {
    float den = 1.f + 2.f * xy + x2 * y2;
    float inv = __fdividef(1.f, den);
    MA r;
    r.a = (1.f + 2.f * xy + y2) * inv;
    r.b = (1.f - x2) * inv;
    r.n2 = r.a * r.a * x2 + 2.f * r.a * r.b * xy + r.b * r.b * y2;
    return r;
}
template <int N>
__device__ __forceinline__ void breduce(float (&vals)[N], float* sm, int tid) {
    __syncthreads();
    #pragma unroll
    for (int i = 0; i < N; i++) {
        float v = vals[i];
        #pragma unroll
        for (int o = 16; o > 0; o >>= 1) v += __shfl_xor_sync(0xffffffffu, v, o);
        if ((tid & 31) == 0) sm[i * 8 + (tid >> 5)] = v;
    }
    __syncthreads();
    #pragma unroll
    for (int i = 0; i < N; i++) {
        float s = 0.f;
        #pragma unroll
        for (int w = 0; w < 8; w++) s += sm[i * 8 + w];
        vals[i] = s;
    }
}

__global__ __launch_bounds__(256)
void hyper_fuse(const float* __restrict__ inp, const float* __restrict__ hprev,
                const float* __restrict__ bz, const float* __restrict__ brv_g,
                const float* __restrict__ bh, float* __restrict__ out)
{
    __shared__ float sm[64];
    const int b = blockIdx.x;
    const int tid = threadIdx.x;
    const size_t rowoff = (size_t)b * HDIM + tid * 4;
    const size_t rowsz = (size_t)BDIM * HDIM;

    float hv[4], xz[4], hz[4], xr[4], hr[4], xh[4], hh[4], xv[4];
    *(float4*)hv = *(const float4*)&hprev[rowoff];
    *(float4*)xv = *(const float4*)&inp[(size_t)b * DDIM + tid * 4];
    *(float4*)xz = *(const float4*)&g_scratch[0 * rowsz + rowoff];
    *(float4*)hz = *(const float4*)&g_scratch[1 * rowsz + rowoff];
    *(float4*)xr = *(const float4*)&g_scratch[2 * rowsz + rowoff];
    *(float4*)hr = *(const float4*)&g_scratch[3 * rowsz + rowoff];
    *(float4*)xh = *(const float4*)&g_scratch[4 * rowsz + rowoff];
    *(float4*)hh = *(const float4*)&g_scratch[5 * rowsz + rowoff];

    float red[8];
    #pragma unroll
    for (int i = 0; i < 8; i++) red[i] = 0.f;
    #pragma unroll
    for (int j = 0; j < 4; j++) {
        red[0] += xv[j] * xv[j];  red[1] += hv[j] * hv[j];
        red[2] += xz[j] * xz[j];  red[3] += hz[j] * hz[j];
        red[4] += xr[j] * xr[j];  red[5] += hr[j] * hr[j];
        red[6] += xh[j] * xh[j];  red[7] += hh[j] * hh[j];
    }
    breduce(red, sm, tid);

    const float hs2 = red[1];
    const float x_n = sqrtf(fmaxf(red[0], 1e-15f));
    const float h_n = sqrtf(fmaxf(red[1], 1e-15f));
    const float qx = __fdividef(artanh_c(x_n), x_n);
    const float qh = __fdividef(artanh_c(h_n), h_n);

    float fxz, az2, fhz, mz2, fxr, ar2, fhr, mr2, fxh, ah2, fhh, mh2;
    {
        float n, t;
        n = sqrtf(fmaxf(red[2], 1e-15f)); t = tanh_fast(n * qx); fxz = __fdividef(t, n); az2 = t * t;
        n = sqrtf(fmaxf(red[3], 1e-15f)); t = tanh_fast(n * qh); fhz = __fdividef(t, n); mz2 = t * t;
        n = sqrtf(fmaxf(red[4], 1e-15f)); t = tanh_fast(n * qx); fxr = __fdividef(t, n); ar2 = t * t;
        n = sqrtf(fmaxf(red[5], 1e-15f)); t = tanh_fast(n * qh); fhr = __fdividef(t, n); mr2 = t * t;
        n = sqrtf(fmaxf(red[6], 1e-15f)); t = tanh_fast(n * qx); fxh = __fdividef(t, n); ah2 = t * t;
        n = sqrtf(fmaxf(red[7], 1e-15f)); t = tanh_fast(n * qh); fhh = __fdividef(t, n); mh2 = t * t;
    }
    float az[4], mz[4], arr[4], mr[4], ah[4], mh[4];
    #pragma unroll
    for (int j = 0; j < 4; j++) {
        az[j]  = fxz * xz[j];  mz[j] = fhz * hz[j];
        arr[j] = fxr * xr[j];  mr[j] = fhr * hr[j];
        ah[j]  = fxh * xh[j];  mh[j] = fhh * hh[j];
    }

    float bzv[4], brv[4], bhv[4];
    *(float4*)bzv = *(const float4*)&bz[tid * 4];
    *(float4*)brv = *(const float4*)&brv_g[tid * 4];
    *(float4*)bhv = *(const float4*)&bh[tid * 4];

    float r2[6];
    #pragma unroll
    for (int i = 0; i < 6; i++) r2[i] = 0.f;
    #pragma unroll
    for (int j = 0; j < 4; j++) {
        r2[0] += mz[j] * bzv[j]; r2[1] += mr[j] * brv[j]; r2[2] += mh[j] * bhv[j];
        r2[3] += bzv[j] * bzv[j]; r2[4] += brv[j] * brv[j]; r2[5] += bhv[j] * bhv[j];
    }
    breduce(r2, sm, tid);

    MA Azc = madd(mz2, r2[3], r2[0]);
    MA Arc = madd(mr2, r2[4], r2[1]);
    MA Ahc = madd(mh2, r2[5], r2[2]);
    float Bz[4], Br[4], Bh[4];
    #pragma unroll
    for (int j = 0; j < 4; j++) {
        Bz[j] = Azc.a * mz[j] + Azc.b * bzv[j];
        Br[j] = Arc.a * mr[j] + Arc.b * brv[j];
        Bh[j] = Ahc.a * mh[j] + Ahc.b * bhv[j];
    }
    const float Bz2 = Azc.n2, Br2 = Arc.n2, Bh2 = Ahc.n2;

    float r3[2]; r3[0] = r3[1] = 0.f;
    #pragma unroll
    for (int j = 0; j < 4; j++) { r3[0] += az[j] * Bz[j]; r3[1] += arr[j] * Br[j]; }
    breduce(r3, sm, tid);

    float zv[4], rv[4];
    {
        MA U = madd(az2, Bz2, r3[0]);
        float n = sqrtf(fmaxf(U.n2, 1e-15f));
        float L = __fdividef(artanh_c(n), n);
        #pragma unroll
        for (int j = 0; j < 4; j++) {
            float u = U.a * az[j] + U.b * Bz[j];
            zv[j] = sigmoid_fast(L * u);
        }
        U = madd(ar2, Br2, r3[1]);
        n = sqrtf(fmaxf(U.n2, 1e-15f));
        L = __fdividef(artanh_c(n), n);
        #pragma unroll
        for (int j = 0; j < 4; j++) {
            float u = U.a * arr[j] + U.b * Br[j];
            rv[j] = sigmoid_fast(L * u);
        }
    }

    float rb[4];
    float r4[1]; r4[0] = 0.f;
    #pragma unroll
    for (int j = 0; j < 4; j++) { rb[j] = rv[j] * Bh[j]; r4[0] += rb[j] * rb[j]; }
    breduce(r4, sm, tid);
    float P[4], P2;
    {
        float Bhn = sqrtf(fmaxf(Bh2, 1e-15f));
        float q = __fdividef(artanh_c(Bhn), Bhn);
        float un = sqrtf(fmaxf(r4[0], 1e-15f));
        float t = tanh_fast(un * q);
        float f = __fdividef(t, un);
        P2 = t * t;
        #pragma unroll
        for (int j = 0; j < 4; j++) P[j] = f * rb[j];
    }

    float r5[1]; r5[0] = 0.f;
    #pragma unroll
    for (int j = 0; j < 4; j++) r5[0] += P[j] * ah[j];
    breduce(r5, sm, tid);
    MA Tc = madd(P2, ah2, r5[0]);
    float Tv[4];
    #pragma unroll
    for (int j = 0; j < 4; j++) Tv[j] = Tc.a * P[j] + Tc.b * ah[j];
    const float T2 = Tc.n2;

    float r6[1]; r6[0] = 0.f;
    #pragma unroll
    for (int j = 0; j < 4; j++) r6[0] += hv[j] * Tv[j];
    breduce(r6, sm, tid);
    MA Mc = madd(hs2, T2, -r6[0]);
    float Mv[4];
    #pragma unroll
    for (int j = 0; j < 4; j++) Mv[j] = -Mc.a * hv[j] + Mc.b * Tv[j];
    const float M2 = Mc.n2;

    float zM[4];
    float r7[1]; r7[0] = 0.f;
    #pragma unroll
    for (int j = 0; j < 4; j++) { zM[j] = zv[j] * Mv[j]; r7[0] += zM[j] * zM[j]; }
    breduce(r7, sm, tid);
    float Q[4], Q2;
    {
        float Mn = sqrtf(fmaxf(M2, 1e-15f));
        float q = __fdividef(artanh_c(Mn), Mn);
        float un = sqrtf(fmaxf(r7[0], 1e-15f));
        float t = tanh_fast(un * q);
        float f = __fdividef(t, un);
        Q2 = t * t;
        #pragma unroll
        for (int j = 0; j < 4; j++) Q[j] = f * zM[j];
    }

    float r8[1]; r8[0] = 0.f;
    #pragma unroll
    for (int j = 0; j < 4; j++) r8[0] += hv[j] * Q[j];
    breduce(r8, sm, tid);
    MA Fc = madd(hs2, Q2, r8[0]);
    float4 o;
    o.x = Fc.a * hv[0] + Fc.b * Q[0];
    o.y = Fc.a * hv[1] + Fc.b * Q[1];
    o.z = Fc.a * hv[2] + Fc.b * Q[2];
    o.w = Fc.a * hv[3] + Fc.b * Q[3];
    *(float4*)&out[rowoff] = o;
}

// ---------------------------------------------------------------------------
// Launch
// ---------------------------------------------------------------------------
extern "C" void kernel_launch(void* const* d_in, const int* in_sizes, int n_in,
                              void* d_out, int out_size)
{
    const float* inp   = (const float*)d_in[0];
    const float* ph    = (const float*)d_in[1];
    const float* w_iz  = (const float*)d_in[2];
    const float* w_hz  = (const float*)d_in[3];
    const float* b_z   = (const float*)d_in[4];
    const float* w_ir  = (const float*)d_in[5];
    const float* w_hr  = (const float*)d_in[6];
    const float* b_r   = (const float*)d_in[7];
    const float* w_ih  = (const float*)d_in[8];
    const float* w_hh  = (const float*)d_in[9];
    const float* b_h   = (const float*)d_in[10];
    float* out = (float*)d_out;

    asplit<<<dim3(BDIM * DDIM / 4 / 256, 2), 256>>>(inp, ph);
    wsplit<<<dim3(32, 32, 6), 256>>>(w_iz, w_hz, w_ir, w_hr, w_ih, w_hh);
    gemm_mma<<<dim3(HDIM / 128, BDIM / 128, 6), 256>>>();
    hyper_fuse<<<BDIM, 256>>>(inp, ph, b_z, b_r, b_h, out);
}

// round 9
// speedup vs baseline: 1.6028x; 1.6028x over previous
#include <cuda_runtime.h>
#include <cuda_fp16.h>
#include <cstdint>
#include <math.h>

#define BDIM 4096
#define DDIM 1024
#define HDIM 1024

// ---------------------------------------------------------------------------
// Device scratch
// ---------------------------------------------------------------------------
__device__ float g_scratch[6ull * BDIM * HDIM];               // 6 GEMM outputs fp32
__device__ __align__(16) __half g_ahi[2ull * BDIM * DDIM];    // act hi (x256) [inp, ph]
__device__ __align__(16) __half g_alo[2ull * BDIM * DDIM];    // act lo (x256)
__device__ __align__(16) __half g_wh[6ull * HDIM * DDIM];     // W^T fp16 (K-major)

#define ASCALE 256.f
#define INV_ASCALE (1.f / 256.f)

// ---------------------------------------------------------------------------
// PTX helpers (sm_80-compatible only)
// ---------------------------------------------------------------------------
__device__ __forceinline__ uint32_t smem_u32(const void* p) {
    uint32_t a;
    asm("{ .reg .u64 t; cvta.to.shared.u64 t, %1; cvt.u32.u64 %0, t; }" : "=r"(a) : "l"(p));
    return a;
}
#define CP16(s, g) \
    asm volatile("cp.async.cg.shared.global [%0], [%1], 16;" :: "r"(s), "l"(g))
#define CP_COMMIT() asm volatile("cp.async.commit_group;" ::: "memory")
#define CP_WAIT(n)  asm volatile("cp.async.wait_group %0;" :: "n"(n) : "memory")

__device__ __forceinline__ void ldm_x4(uint32_t* r, uint32_t addr) {
    asm volatile("ldmatrix.sync.aligned.m8n8.x4.shared.b16 {%0,%1,%2,%3}, [%4];"
                 : "=r"(r[0]), "=r"(r[1]), "=r"(r[2]), "=r"(r[3]) : "r"(addr));
}
__device__ __forceinline__ void mma_f16(float* d, const uint32_t* a,
                                        uint32_t b0, uint32_t b1) {
    asm volatile(
        "mma.sync.aligned.m16n8k16.row.col.f32.f16.f16.f32 "
        "{%0,%1,%2,%3}, {%4,%5,%6,%7}, {%8,%9}, {%0,%1,%2,%3};"
        : "+f"(d[0]), "+f"(d[1]), "+f"(d[2]), "+f"(d[3])
        : "r"(a[0]), "r"(a[1]), "r"(a[2]), "r"(a[3]), "r"(b0), "r"(b1));
}
// SW64 swizzle for 64-byte rows (conflict-free ldmatrix, proven in R5)
__device__ __forceinline__ uint32_t swz64(uint32_t off) {
    return off ^ ((off >> 3) & 0x30);
}

// ---------------------------------------------------------------------------
// Prep: scale activations by 256, split into fp16 hi/lo
// ---------------------------------------------------------------------------
__global__ __launch_bounds__(256)
void asplit(const float* __restrict__ inp, const float* __restrict__ ph)
{
    const int t = blockIdx.y;
    const float* src = t ? ph : inp;
    size_t base = ((size_t)blockIdx.x * 256 + threadIdx.x) * 4;
    float4 v = *(const float4*)&src[base];
    __half h[4], l[4];
    float vv[4] = {v.x * ASCALE, v.y * ASCALE, v.z * ASCALE, v.w * ASCALE};
    #pragma unroll
    for (int i = 0; i < 4; i++) {
        h[i] = __float2half_rn(vv[i]);
        l[i] = __float2half_rn(vv[i] - __half2float(h[i]));
    }
    size_t off = (size_t)t * BDIM * DDIM + base;
    *(uint2*)&g_ahi[off] = *(uint2*)h;
    *(uint2*)&g_alo[off] = *(uint2*)l;
}

// ---------------------------------------------------------------------------
// Prep: transpose weights to K-major fp16 [N][K]
// ---------------------------------------------------------------------------
__global__ __launch_bounds__(256)
void wsplit(const float* __restrict__ w0, const float* __restrict__ w1,
            const float* __restrict__ w2, const float* __restrict__ w3,
            const float* __restrict__ w4, const float* __restrict__ w5)
{
    __shared__ float t[32][33];
    const int z = blockIdx.z;
    const float* W;
    switch (z) { case 0: W = w0; break; case 1: W = w1; break; case 2: W = w2; break;
                 case 3: W = w3; break; case 4: W = w4; break; default: W = w5; }
    const int n0 = blockIdx.x * 32, k0 = blockIdx.y * 32;
    const int tx = threadIdx.x & 31, ty = threadIdx.x >> 5;   // 32 x 8
    #pragma unroll
    for (int i = 0; i < 4; i++)
        t[ty + 8 * i][tx] = W[(size_t)(k0 + ty + 8 * i) * HDIM + n0 + tx];
    __syncthreads();
    __half* H = g_wh + (size_t)z * HDIM * DDIM;
    #pragma unroll
    for (int i = 0; i < 4; i++) {
        float v = t[tx][ty + 8 * i];
        H[(size_t)(n0 + ty + 8 * i) * DDIM + k0 + tx] = __float2half_rn(v);
    }
}

// ---------------------------------------------------------------------------
// mma.sync GEMM: C[z] (BxH) = A @ W[z], 2-term scaled-fp16 split.
// R5-proven structure: CTA 128x128, 8 warps (4M x 2N), warp tile 32x64,
// K32 chunks, double buffer, one sync per chunk.
// 64 chunks = 2 term passes x 32 K-chunks.
// ---------------------------------------------------------------------------
#define STAGE_BYTES 16384        // A 8K | B 8K   (64B rows, SW64 swizzle)
#define NCHUNK 64

__device__ __forceinline__ void load_chunk(uint32_t sb, int c,
    const __half* __restrict__ ahi, const __half* __restrict__ alo,
    const __half* __restrict__ bh, int tid)
{
    const int term = c >> 5;            // 0: ahi pass, 1: alo pass
    const int k0 = (c & 31) * 32;
    const __half* A = term ? alo : ahi;
    #pragma unroll
    for (int it = 0; it < 2; it++) {
        int op = tid + it * 256;        // 0..511 : r = op>>2 (0..127), kk = op&3
        int r = op >> 2, kk = op & 3;
        uint32_t so = swz64((uint32_t)(r * 64 + kk * 16));
        CP16(sb + so,        A + (size_t)r * DDIM + k0 + kk * 8);
        CP16(sb + 8192 + so, bh + (size_t)r * DDIM + k0 + kk * 8);
    }
}

__global__ __launch_bounds__(256, 2)
void gemm_mma()
{
    __shared__ __align__(1024) char smem_buf[2][STAGE_BYTES];
    const uint32_t sb = smem_u32(smem_buf);
    const int tid = threadIdx.x, wid = tid >> 5, lid = tid & 31;
    const int wm = wid >> 1;            // 0..3 -> M offset 32*wm
    const int wn = wid & 1;             // 0..1 -> N offset 64*wn
    const int z = blockIdx.z;
    const int bm = blockIdx.y * 128;
    const int bn = blockIdx.x * 128;
    const int act = z & 1;

    const __half* ahi = g_ahi + (size_t)act * BDIM * DDIM + (size_t)bm * DDIM;
    const __half* alo = g_alo + (size_t)act * BDIM * DDIM + (size_t)bm * DDIM;
    const __half* bh  = g_wh + (size_t)z * HDIM * DDIM + (size_t)bn * DDIM;

    float acc[2][8][4];
    #pragma unroll
    for (int i = 0; i < 2; i++)
        #pragma unroll
        for (int n = 0; n < 8; n++)
            #pragma unroll
            for (int q = 0; q < 4; q++) acc[i][n][q] = 0.f;

    load_chunk(sb, 0, ahi, alo, bh, tid);
    CP_COMMIT();

    const int lrow = lid & 15;          // row within 16-row tile
    const int lhalf = (lid >> 4) * 16;  // 16B half select

    for (int c = 0; c < NCHUNK; c++) {
        const uint32_t sA = sb + (c & 1) * STAGE_BYTES;
        const uint32_t sB = sA + 8192;
        if (c + 1 < NCHUNK) {
            load_chunk(sb + ((c + 1) & 1) * STAGE_BYTES, c + 1, ahi, alo, bh, tid);
            CP_COMMIT();
            CP_WAIT(1);
        } else {
            CP_WAIT(0);
        }
        __syncthreads();

        #pragma unroll
        for (int ks = 0; ks < 2; ks++) {
            const uint32_t kcol = (uint32_t)(ks * 32 + lhalf);
            uint32_t a[2][4];
            #pragma unroll
            for (int i = 0; i < 2; i++) {
                uint32_t off = (uint32_t)((32 * wm + 16 * i + lrow) * 64) + kcol;
                ldm_x4(a[i], sA + swz64(off));
            }
            uint32_t b[4][4];
            #pragma unroll
            for (int j = 0; j < 4; j++) {
                uint32_t off = (uint32_t)((64 * wn + 16 * j + lrow) * 64) + kcol;
                ldm_x4(b[j], sB + swz64(off));
            }
            #pragma unroll
            for (int i = 0; i < 2; i++)
                #pragma unroll
                for (int n = 0; n < 8; n++) {
                    const int g = n >> 1, s = n & 1;
                    mma_f16(acc[i][n], a[i], b[g][s], b[g][s + 2]);
                }
        }
        __syncthreads();
    }

    // Epilogue: undo the x256 activation scale.
    float* C = g_scratch + (size_t)z * BDIM * HDIM;
    const int erow = lid >> 2, ecol = (lid & 3) * 2;
    #pragma unroll
    for (int i = 0; i < 2; i++) {
        #pragma unroll
        for (int n = 0; n < 8; n++) {
            const int row = bm + 32 * wm + 16 * i + erow;
            const int col = bn + 64 * wn + 8 * n + ecol;
            float2 v0 = make_float2(acc[i][n][0] * INV_ASCALE, acc[i][n][1] * INV_ASCALE);
            float2 v1 = make_float2(acc[i][n][2] * INV_ASCALE, acc[i][n][3] * INV_ASCALE);
            *(float2*)&C[(size_t)row * HDIM + col]       = v0;
            *(float2*)&C[(size_t)(row + 8) * HDIM + col] = v1;
        }
    }
}

// ---------------------------------------------------------------------------
// Hyperbolic elementwise stage (fast-math, validated in R7: 62.7us)
// ---------------------------------------------------------------------------
__device__ __forceinline__ float artanh_c(float v) {
    v = fminf(fmaxf(v, -1.f + 1e-5f), 1.f - 1e-5f);
    return 0.5f * __logf(__fdividef(1.f + v, 1.f - v));
}
__device__ __forceinline__ float tanh_fast(float x) {
    float e = __expf(-2.f * x);
    return __fdividef(1.f - e, 1.f + e);
}
__device__ __forceinline__ float sigmoid_fast(float x) {
    return __fdividef(1.f, 1.f + __expf(-x));
}
struct MA { float a, b, n2; };
__device__ __forceinline__ MA madd(float x2, float y2, float xy) {
    float den = 1.f + 2.f * xy + x2 * y2;
    float inv = __fdividef(1.f, den);
    MA r;
    r.a = (1.f + 2.f * xy + y2) * inv;
    r.b = (1.f - x2) * inv;
    r.n2 = r.a * r.a * x2 + 2.f * r.a * r.b * xy + r.b * r.b * y2;
    return r;
}
template <int N>
__device__ __forceinline__ void breduce(float (&vals)[N], float* sm, int tid) {
    __syncthreads();
    #pragma unroll
    for (int i = 0; i < N; i++) {
        float v = vals[i];
        #pragma unroll
        for (int o = 16; o > 0; o >>= 1) v += __shfl_xor_sync(0xffffffffu, v, o);
        if ((tid & 31) == 0) sm[i * 8 + (tid >> 5)] = v;
    }
    __syncthreads();
    #pragma unroll
    for (int i = 0; i < N; i++) {
        float s = 0.f;
        #pragma unroll
        for (int w = 0; w < 8; w++) s += sm[i * 8 + w];
        vals[i] = s;
    }
}

__global__ __launch_bounds__(256)
void hyper_fuse(const float* __restrict__ inp, const float* __restrict__ hprev,
                const float* __restrict__ bz, const float* __restrict__ brv_g,
                const float* __restrict__ bh, float* __restrict__ out)
{
    __shared__ float sm[64];
    const int b = blockIdx.x;
    const int tid = threadIdx.x;
    const size_t rowoff = (size_t)b * HDIM + tid * 4;
    const size_t rowsz = (size_t)BDIM * HDIM;

    float hv[4], xz[4], hz[4], xr[4], hr[4], xh[4], hh[4], xv[4];
    *(float4*)hv = *(const float4*)&hprev[rowoff];
    *(float4*)xv = *(const float4*)&inp[(size_t)b * DDIM + tid * 4];
    *(float4*)xz = *(const float4*)&g_scratch[0 * rowsz + rowoff];
    *(float4*)hz = *(const float4*)&g_scratch[1 * rowsz + rowoff];
    *(float4*)xr = *(const float4*)&g_scratch[2 * rowsz + rowoff];
    *(float4*)hr = *(const float4*)&g_scratch[3 * rowsz + rowoff];
    *(float4*)xh = *(const float4*)&g_scratch[4 * rowsz + rowoff];
    *(float4*)hh = *(const float4*)&g_scratch[5 * rowsz + rowoff];

    float red[8];
    #pragma unroll
    for (int i = 0; i < 8; i++) red[i] = 0.f;
    #pragma unroll
    for (int j = 0; j < 4; j++) {
        red[0] += xv[j] * xv[j];  red[1] += hv[j] * hv[j];
        red[2] += xz[j] * xz[j];  red[3] += hz[j] * hz[j];
        red[4] += xr[j] * xr[j];  red[5] += hr[j] * hr[j];
        red[6] += xh[j] * xh[j];  red[7] += hh[j] * hh[j];
    }
    breduce(red, sm, tid);

    const float hs2 = red[1];
    const float x_n = sqrtf(fmaxf(red[0], 1e-15f));
    const float h_n = sqrtf(fmaxf(red[1], 1e-15f));
    const float qx = __fdividef(artanh_c(x_n), x_n);
    const float qh = __fdividef(artanh_c(h_n), h_n);

    float fxz, az2, fhz, mz2, fxr, ar2, fhr, mr2, fxh, ah2, fhh, mh2;
    {
        float n, t;
        n = sqrtf(fmaxf(red[2], 1e-15f)); t = tanh_fast(n * qx); fxz = __fdividef(t, n); az2 = t * t;
        n = sqrtf(fmaxf(red[3], 1e-15f)); t = tanh_fast(n * qh); fhz = __fdividef(t, n); mz2 = t * t;
        n = sqrtf(fmaxf(red[4], 1e-15f)); t = tanh_fast(n * qx); fxr = __fdividef(t, n); ar2 = t * t;
        n = sqrtf(fmaxf(red[5], 1e-15f)); t = tanh_fast(n * qh); fhr = __fdividef(t, n); mr2 = t * t;
        n = sqrtf(fmaxf(red[6], 1e-15f)); t = tanh_fast(n * qx); fxh = __fdividef(t, n); ah2 = t * t;
        n = sqrtf(fmaxf(red[7], 1e-15f)); t = tanh_fast(n * qh); fhh = __fdividef(t, n); mh2 = t * t;
    }
    float az[4], mz[4], arr[4], mr[4], ah[4], mh[4];
    #pragma unroll
    for (int j = 0; j < 4; j++) {
        az[j]  = fxz * xz[j];  mz[j] = fhz * hz[j];
        arr[j] = fxr * xr[j];  mr[j] = fhr * hr[j];
        ah[j]  = fxh * xh[j];  mh[j] = fhh * hh[j];
    }

    float bzv[4], brv[4], bhv[4];
    *(float4*)bzv = *(const float4*)&bz[tid * 4];
    *(float4*)brv = *(const float4*)&brv_g[tid * 4];
    *(float4*)bhv = *(const float4*)&bh[tid * 4];

    float r2[6];
    #pragma unroll
    for (int i = 0; i < 6; i++) r2[i] = 0.f;
    #pragma unroll
    for (int j = 0; j < 4; j++) {
        r2[0] += mz[j] * bzv[j]; r2[1] += mr[j] * brv[j]; r2[2] += mh[j] * bhv[j];
        r2[3] += bzv[j] * bzv[j]; r2[4] += brv[j] * brv[j]; r2[5] += bhv[j] * bhv[j];
    }
    breduce(r2, sm, tid);

    MA Azc = madd(mz2, r2[3], r2[0]);
    MA Arc = madd(mr2, r2[4], r2[1]);
    MA Ahc = madd(mh2, r2[5], r2[2]);
    float Bz[4], Br[4], Bh[4];
    #pragma unroll
    for (int j = 0; j < 4; j++) {
        Bz[j] = Azc.a * mz[j] + Azc.b * bzv[j];
        Br[j] = Arc.a * mr[j] + Arc.b * brv[j];
        Bh[j] = Ahc.a * mh[j] + Ahc.b * bhv[j];
    }
    const float Bz2 = Azc.n2, Br2 = Arc.n2, Bh2 = Ahc.n2;

    float r3[2]; r3[0] = r3[1] = 0.f;
    #pragma unroll
    for (int j = 0; j < 4; j++) { r3[0] += az[j] * Bz[j]; r3[1] += arr[j] * Br[j]; }
    breduce(r3, sm, tid);

    float zv[4], rv[4];
    {
        MA U = madd(az2, Bz2, r3[0]);
        float n = sqrtf(fmaxf(U.n2, 1e-15f));
        float L = __fdividef(artanh_c(n), n);
        #pragma unroll
        for (int j = 0; j < 4; j++) {
            float u = U.a * az[j] + U.b * Bz[j];
            zv[j] = sigmoid_fast(L * u);
        }
        U = madd(ar2, Br2, r3[1]);
        n = sqrtf(fmaxf(U.n2, 1e-15f));
        L = __fdividef(artanh_c(n), n);
        #pragma unroll
        for (int j = 0; j < 4; j++) {
            float u = U.a * arr[j] + U.b * Br[j];
            rv[j] = sigmoid_fast(L * u);
        }
    }

    float rb[4];
    float r4[1]; r4[0] = 0.f;
    #pragma unroll
    for (int j = 0; j < 4; j++) { rb[j] = rv[j] * Bh[j]; r4[0] += rb[j] * rb[j]; }
    breduce(r4, sm, tid);
    float P[4], P2;
    {
        float Bhn = sqrtf(fmaxf(Bh2, 1e-15f));
        float q = __fdividef(artanh_c(Bhn), Bhn);
        float un = sqrtf(fmaxf(r4[0], 1e-15f));
        float t = tanh_fast(un * q);
        float f = __fdividef(t, un);
        P2 = t * t;
        #pragma unroll
        for (int j = 0; j < 4; j++) P[j] = f * rb[j];
    }

    float r5[1]; r5[0] = 0.f;
    #pragma unroll
    for (int j = 0; j < 4; j++) r5[0] += P[j] * ah[j];
    breduce(r5, sm, tid);
    MA Tc = madd(P2, ah2, r5[0]);
    float Tv[4];
    #pragma unroll
    for (int j = 0; j < 4; j++) Tv[j] = Tc.a * P[j] + Tc.b * ah[j];
    const float T2 = Tc.n2;

    float r6[1]; r6[0] = 0.f;
    #pragma unroll
    for (int j = 0; j < 4; j++) r6[0] += hv[j] * Tv[j];
    breduce(r6, sm, tid);
    MA Mc = madd(hs2, T2, -r6[0]);
    float Mv[4];
    #pragma unroll
    for (int j = 0; j < 4; j++) Mv[j] = -Mc.a * hv[j] + Mc.b * Tv[j];
    const float M2 = Mc.n2;

    float zM[4];
    float r7[1]; r7[0] = 0.f;
    #pragma unroll
    for (int j = 0; j < 4; j++) { zM[j] = zv[j] * Mv[j]; r7[0] += zM[j] * zM[j]; }
    breduce(r7, sm, tid);
    float Q[4], Q2;
    {
        float Mn = sqrtf(fmaxf(M2, 1e-15f));
        float q = __fdividef(artanh_c(Mn), Mn);
        float un = sqrtf(fmaxf(r7[0], 1e-15f));
        float t = tanh_fast(un * q);
        float f = __fdividef(t, un);
        Q2 = t * t;
        #pragma unroll
        for (int j = 0; j < 4; j++) Q[j] = f * zM[j];
    }

    float r8[1]; r8[0] = 0.f;
    #pragma unroll
    for (int j = 0; j < 4; j++) r8[0] += hv[j] * Q[j];
    breduce(r8, sm, tid);
    MA Fc = madd(hs2, Q2, r8[0]);
    float4 o;
    o.x = Fc.a * hv[0] + Fc.b * Q[0];
    o.y = Fc.a * hv[1] + Fc.b * Q[1];
    o.z = Fc.a * hv[2] + Fc.b * Q[2];
    o.w = Fc.a * hv[3] + Fc.b * Q[3];
    *(float4*)&out[rowoff] = o;
}

// ---------------------------------------------------------------------------
// Launch
// ---------------------------------------------------------------------------
extern "C" void kernel_launch(void* const* d_in, const int* in_sizes, int n_in,
                              void* d_out, int out_size)
{
    const float* inp   = (const float*)d_in[0];
    const float* ph    = (const float*)d_in[1];
    const float* w_iz  = (const float*)d_in[2];
    const float* w_hz  = (const float*)d_in[3];
    const float* b_z   = (const float*)d_in[4];
    const float* w_ir  = (const float*)d_in[5];
    const float* w_hr  = (const float*)d_in[6];
    const float* b_r   = (const float*)d_in[7];
    const float* w_ih  = (const float*)d_in[8];
    const float* w_hh  = (const float*)d_in[9];
    const float* b_h   = (const float*)d_in[10];
    float* out = (float*)d_out;

    asplit<<<dim3(BDIM * DDIM / 4 / 256, 2), 256>>>(inp, ph);
    wsplit<<<dim3(32, 32, 6), 256>>>(w_iz, w_hz, w_ir, w_hr, w_ih, w_hh);
    gemm_mma<<<dim3(HDIM / 128, BDIM / 128, 6), 256>>>();
    hyper_fuse<<<BDIM, 256>>>(inp, ph, b_z, b_r, b_h, out);
}

// round 10
// speedup vs baseline: 1.6589x; 1.0350x over previous
#include <cuda_runtime.h>
#include <cuda_fp16.h>
#include <cstdint>
#include <math.h>

#define BDIM 4096
#define DDIM 1024
#define HDIM 1024

// ---------------------------------------------------------------------------
// Device scratch
// ---------------------------------------------------------------------------
__device__ float g_scratch[6ull * BDIM * HDIM];               // 6 GEMM outputs fp32
__device__ __align__(16) __half g_ahi[2ull * BDIM * DDIM];    // act hi (x256) [inp, ph]
__device__ __align__(16) __half g_alo[2ull * BDIM * DDIM];    // act lo (x256)
__device__ __align__(16) __half g_wh[6ull * HDIM * DDIM];     // W^T fp16 (K-major)

#define ASCALE 256.f
#define INV_ASCALE (1.f / 256.f)

// ---------------------------------------------------------------------------
// PTX helpers (sm_80-compatible only)
// ---------------------------------------------------------------------------
__device__ __forceinline__ uint32_t smem_u32(const void* p) {
    uint32_t a;
    asm("{ .reg .u64 t; cvta.to.shared.u64 t, %1; cvt.u32.u64 %0, t; }" : "=r"(a) : "l"(p));
    return a;
}
#define CP16(s, g) \
    asm volatile("cp.async.cg.shared.global [%0], [%1], 16;" :: "r"(s), "l"(g))
#define CP_COMMIT() asm volatile("cp.async.commit_group;" ::: "memory")
#define CP_WAIT(n)  asm volatile("cp.async.wait_group %0;" :: "n"(n) : "memory")

__device__ __forceinline__ void ldm_x4(uint32_t* r, uint32_t addr) {
    asm volatile("ldmatrix.sync.aligned.m8n8.x4.shared.b16 {%0,%1,%2,%3}, [%4];"
                 : "=r"(r[0]), "=r"(r[1]), "=r"(r[2]), "=r"(r[3]) : "r"(addr));
}
__device__ __forceinline__ void mma_f16(float* d, const uint32_t* a,
                                        uint32_t b0, uint32_t b1) {
    asm volatile(
        "mma.sync.aligned.m16n8k16.row.col.f32.f16.f16.f32 "
        "{%0,%1,%2,%3}, {%4,%5,%6,%7}, {%8,%9}, {%0,%1,%2,%3};"
        : "+f"(d[0]), "+f"(d[1]), "+f"(d[2]), "+f"(d[3])
        : "r"(a[0]), "r"(a[1]), "r"(a[2]), "r"(a[3]), "r"(b0), "r"(b1));
}
// SW64 swizzle for 64-byte rows (conflict-free ldmatrix, proven in R5/R9)
__device__ __forceinline__ uint32_t swz64(uint32_t off) {
    return off ^ ((off >> 3) & 0x30);
}

// ---------------------------------------------------------------------------
// Prep: scale activations by 256, split into fp16 hi/lo
// ---------------------------------------------------------------------------
__global__ __launch_bounds__(256)
void asplit(const float* __restrict__ inp, const float* __restrict__ ph)
{
    const int t = blockIdx.y;
    const float* src = t ? ph : inp;
    size_t base = ((size_t)blockIdx.x * 256 + threadIdx.x) * 4;
    float4 v = *(const float4*)&src[base];
    __half h[4], l[4];
    float vv[4] = {v.x * ASCALE, v.y * ASCALE, v.z * ASCALE, v.w * ASCALE};
    #pragma unroll
    for (int i = 0; i < 4; i++) {
        h[i] = __float2half_rn(vv[i]);
        l[i] = __float2half_rn(vv[i] - __half2float(h[i]));
    }
    size_t off = (size_t)t * BDIM * DDIM + base;
    *(uint2*)&g_ahi[off] = *(uint2*)h;
    *(uint2*)&g_alo[off] = *(uint2*)l;
}

// ---------------------------------------------------------------------------
// Prep: transpose weights to K-major fp16 [N][K]
// ---------------------------------------------------------------------------
__global__ __launch_bounds__(256)
void wsplit(const float* __restrict__ w0, const float* __restrict__ w1,
            const float* __restrict__ w2, const float* __restrict__ w3,
            const float* __restrict__ w4, const float* __restrict__ w5)
{
    __shared__ float t[32][33];
    const int z = blockIdx.z;
    const float* W;
    switch (z) { case 0: W = w0; break; case 1: W = w1; break; case 2: W = w2; break;
                 case 3: W = w3; break; case 4: W = w4; break; default: W = w5; }
    const int n0 = blockIdx.x * 32, k0 = blockIdx.y * 32;
    const int tx = threadIdx.x & 31, ty = threadIdx.x >> 5;   // 32 x 8
    #pragma unroll
    for (int i = 0; i < 4; i++)
        t[ty + 8 * i][tx] = W[(size_t)(k0 + ty + 8 * i) * HDIM + n0 + tx];
    __syncthreads();
    __half* H = g_wh + (size_t)z * HDIM * DDIM;
    #pragma unroll
    for (int i = 0; i < 4; i++) {
        float v = t[tx][ty + 8 * i];
        H[(size_t)(n0 + ty + 8 * i) * DDIM + k0 + tx] = __float2half_rn(v);
    }
}

// ---------------------------------------------------------------------------
// mma.sync GEMM: C[z] (BxH) = A @ W[z], 2-term scaled-fp16 split,
// terms INTERLEAVED in one K sweep (B fragments reused by both terms).
// R9-verbatim skeleton: CTA 128x128, 8 warps (4M x 2N), warp tile 32x64,
// K32 chunks, double buffer, CP_WAIT(1), two syncs per chunk.
// Stage = {A_hi 8K | A_lo 8K | B 8K} = 24KB; 2 stages = 48KB static smem.
// ---------------------------------------------------------------------------
#define STAGE_BYTES 24576
#define NCHUNK 32

__device__ __forceinline__ void load_chunk(uint32_t sb, int c,
    const __half* __restrict__ ahi, const __half* __restrict__ alo,
    const __half* __restrict__ bh, int tid)
{
    const int k0 = c * 32;
    #pragma unroll
    for (int it = 0; it < 2; it++) {
        int op = tid + it * 256;        // 0..511 : r = op>>2 (0..127), kk = op&3
        int r = op >> 2, kk = op & 3;
        uint32_t so = swz64((uint32_t)(r * 64 + kk * 16));
        size_t go = (size_t)r * DDIM + k0 + kk * 8;
        CP16(sb + so,         ahi + go);
        CP16(sb + 8192 + so,  alo + go);
        CP16(sb + 16384 + so, bh + go);
    }
}

__global__ __launch_bounds__(256, 2)
void gemm_mma()
{
    __shared__ __align__(1024) char smem_buf[2][STAGE_BYTES];
    const uint32_t sb = smem_u32(smem_buf);
    const int tid = threadIdx.x, wid = tid >> 5, lid = tid & 31;
    const int wm = wid >> 1;            // 0..3 -> M offset 32*wm
    const int wn = wid & 1;             // 0..1 -> N offset 64*wn
    const int z = blockIdx.z;
    const int bm = blockIdx.y * 128;
    const int bn = blockIdx.x * 128;
    const int act = z & 1;

    const __half* ahi = g_ahi + (size_t)act * BDIM * DDIM + (size_t)bm * DDIM;
    const __half* alo = g_alo + (size_t)act * BDIM * DDIM + (size_t)bm * DDIM;
    const __half* bh  = g_wh + (size_t)z * HDIM * DDIM + (size_t)bn * DDIM;

    float acc[2][8][4];
    #pragma unroll
    for (int i = 0; i < 2; i++)
        #pragma unroll
        for (int n = 0; n < 8; n++)
            #pragma unroll
            for (int q = 0; q < 4; q++) acc[i][n][q] = 0.f;

    load_chunk(sb, 0, ahi, alo, bh, tid);
    CP_COMMIT();

    const int lrow = lid & 15;          // row within 16-row tile
    const int lhalf = (lid >> 4) * 16;  // 16B half select

    for (int c = 0; c < NCHUNK; c++) {
        const uint32_t sA = sb + (c & 1) * STAGE_BYTES;       // A_hi
        const uint32_t sAl = sA + 8192;                        // A_lo
        const uint32_t sB = sA + 16384;                        // B
        if (c + 1 < NCHUNK) {
            load_chunk(sb + ((c + 1) & 1) * STAGE_BYTES, c + 1, ahi, alo, bh, tid);
            CP_COMMIT();
            CP_WAIT(1);
        } else {
            CP_WAIT(0);
        }
        __syncthreads();

        #pragma unroll
        for (int ks = 0; ks < 2; ks++) {
            const uint32_t kcol = (uint32_t)(ks * 32 + lhalf);
            uint32_t b[4][4];
            #pragma unroll
            for (int j = 0; j < 4; j++) {
                uint32_t off = (uint32_t)((64 * wn + 16 * j + lrow) * 64) + kcol;
                ldm_x4(b[j], sB + swz64(off));
            }
            uint32_t a[2][4];
            // term0: A_hi * B
            #pragma unroll
            for (int i = 0; i < 2; i++) {
                uint32_t off = (uint32_t)((32 * wm + 16 * i + lrow) * 64) + kcol;
                ldm_x4(a[i], sA + swz64(off));
            }
            #pragma unroll
            for (int i = 0; i < 2; i++)
                #pragma unroll
                for (int n = 0; n < 8; n++) {
                    const int g = n >> 1, s = n & 1;
                    mma_f16(acc[i][n], a[i], b[g][s], b[g][s + 2]);
                }
            // term1: A_lo * B (reuse b fragments, recycle a registers)
            #pragma unroll
            for (int i = 0; i < 2; i++) {
                uint32_t off = (uint32_t)((32 * wm + 16 * i + lrow) * 64) + kcol;
                ldm_x4(a[i], sAl + swz64(off));
            }
            #pragma unroll
            for (int i = 0; i < 2; i++)
                #pragma unroll
                for (int n = 0; n < 8; n++) {
                    const int g = n >> 1, s = n & 1;
                    mma_f16(acc[i][n], a[i], b[g][s], b[g][s + 2]);
                }
        }
        __syncthreads();
    }

    // Epilogue: undo the x256 activation scale.
    float* C = g_scratch + (size_t)z * BDIM * HDIM;
    const int erow = lid >> 2, ecol = (lid & 3) * 2;
    #pragma unroll
    for (int i = 0; i < 2; i++) {
        #pragma unroll
        for (int n = 0; n < 8; n++) {
            const int row = bm + 32 * wm + 16 * i + erow;
            const int col = bn + 64 * wn + 8 * n + ecol;
            float2 v0 = make_float2(acc[i][n][0] * INV_ASCALE, acc[i][n][1] * INV_ASCALE);
            float2 v1 = make_float2(acc[i][n][2] * INV_ASCALE, acc[i][n][3] * INV_ASCALE);
            *(float2*)&C[(size_t)row * HDIM + col]       = v0;
            *(float2*)&C[(size_t)(row + 8) * HDIM + col] = v1;
        }
    }
}

// ---------------------------------------------------------------------------
// Hyperbolic elementwise stage (fast-math, validated: 62.7us)
// ---------------------------------------------------------------------------
__device__ __forceinline__ float artanh_c(float v) {
    v = fminf(fmaxf(v, -1.f + 1e-5f), 1.f - 1e-5f);
    return 0.5f * __logf(__fdividef(1.f + v, 1.f - v));
}
__device__ __forceinline__ float tanh_fast(float x) {
    float e = __expf(-2.f * x);
    return __fdividef(1.f - e, 1.f + e);
}
__device__ __forceinline__ float sigmoid_fast(float x) {
    return __fdividef(1.f, 1.f + __expf(-x));
}
struct MA { float a, b, n2; };
__device__ __forceinline__ MA madd(float x2, float y2, float xy) {
    float den = 1.f + 2.f * xy + x2 * y2;
    float inv = __fdividef(1.f, den);
    MA r;
    r.a = (1.f + 2.f * xy + y2) * inv;
    r.b = (1.f - x2) * inv;
    r.n2 = r.a * r.a * x2 + 2.f * r.a * r.b * xy + r.b * r.b * y2;
    return r;
}
template <int N>
__device__ __forceinline__ void breduce(float (&vals)[N], float* sm, int tid) {
    __syncthreads();
    #pragma unroll
    for (int i = 0; i < N; i++) {
        float v = vals[i];
        #pragma unroll
        for (int o = 16; o > 0; o >>= 1) v += __shfl_xor_sync(0xffffffffu, v, o);
        if ((tid & 31) == 0) sm[i * 8 + (tid >> 5)] = v;
    }
    __syncthreads();
    #pragma unroll
    for (int i = 0; i < N; i++) {
        float s = 0.f;
        #pragma unroll
        for (int w = 0; w < 8; w++) s += sm[i * 8 + w];
        vals[i] = s;
    }
}

__global__ __launch_bounds__(256)
void hyper_fuse(const float* __restrict__ inp, const float* __restrict__ hprev,
                const float* __restrict__ bz, const float* __restrict__ brv_g,
                const float* __restrict__ bh, float* __restrict__ out)
{
    __shared__ float sm[64];
    const int b = blockIdx.x;
    const int tid = threadIdx.x;
    const size_t rowoff = (size_t)b * HDIM + tid * 4;
    const size_t rowsz = (size_t)BDIM * HDIM;

    float hv[4], xz[4], hz[4], xr[4], hr[4], xh[4], hh[4], xv[4];
    *(float4*)hv = *(const float4*)&hprev[rowoff];
    *(float4*)xv = *(const float4*)&inp[(size_t)b * DDIM + tid * 4];
    *(float4*)xz = *(const float4*)&g_scratch[0 * rowsz + rowoff];
    *(float4*)hz = *(const float4*)&g_scratch[1 * rowsz + rowoff];
    *(float4*)xr = *(const float4*)&g_scratch[2 * rowsz + rowoff];
    *(float4*)hr = *(const float4*)&g_scratch[3 * rowsz + rowoff];
    *(float4*)xh = *(const float4*)&g_scratch[4 * rowsz + rowoff];
    *(float4*)hh = *(const float4*)&g_scratch[5 * rowsz + rowoff];

    float red[8];
    #pragma unroll
    for (int i = 0; i < 8; i++) red[i] = 0.f;
    #pragma unroll
    for (int j = 0; j < 4; j++) {
        red[0] += xv[j] * xv[j];  red[1] += hv[j] * hv[j];
        red[2] += xz[j] * xz[j];  red[3] += hz[j] * hz[j];
        red[4] += xr[j] * xr[j];  red[5] += hr[j] * hr[j];
        red[6] += xh[j] * xh[j];  red[7] += hh[j] * hh[j];
    }
    breduce(red, sm, tid);

    const float hs2 = red[1];
    const float x_n = sqrtf(fmaxf(red[0], 1e-15f));
    const float h_n = sqrtf(fmaxf(red[1], 1e-15f));
    const float qx = __fdividef(artanh_c(x_n), x_n);
    const float qh = __fdividef(artanh_c(h_n), h_n);

    float fxz, az2, fhz, mz2, fxr, ar2, fhr, mr2, fxh, ah2, fhh, mh2;
    {
        float n, t;
        n = sqrtf(fmaxf(red[2], 1e-15f)); t = tanh_fast(n * qx); fxz = __fdividef(t, n); az2 = t * t;
        n = sqrtf(fmaxf(red[3], 1e-15f)); t = tanh_fast(n * qh); fhz = __fdividef(t, n); mz2 = t * t;
        n = sqrtf(fmaxf(red[4], 1e-15f)); t = tanh_fast(n * qx); fxr = __fdividef(t, n); ar2 = t * t;
        n = sqrtf(fmaxf(red[5], 1e-15f)); t = tanh_fast(n * qh); fhr = __fdividef(t, n); mr2 = t * t;
        n = sqrtf(fmaxf(red[6], 1e-15f)); t = tanh_fast(n * qx); fxh = __fdividef(t, n); ah2 = t * t;
        n = sqrtf(fmaxf(red[7], 1e-15f)); t = tanh_fast(n * qh); fhh = __fdividef(t, n); mh2 = t * t;
    }
    float az[4], mz[4], arr[4], mr[4], ah[4], mh[4];
    #pragma unroll
    for (int j = 0; j < 4; j++) {
        az[j]  = fxz * xz[j];  mz[j] = fhz * hz[j];
        arr[j] = fxr * xr[j];  mr[j] = fhr * hr[j];
        ah[j]  = fxh * xh[j];  mh[j] = fhh * hh[j];
    }

    float bzv[4], brv[4], bhv[4];
    *(float4*)bzv = *(const float4*)&bz[tid * 4];
    *(float4*)brv = *(const float4*)&brv_g[tid * 4];
    *(float4*)bhv = *(const float4*)&bh[tid * 4];

    float r2[6];
    #pragma unroll
    for (int i = 0; i < 6; i++) r2[i] = 0.f;
    #pragma unroll
    for (int j = 0; j < 4; j++) {
        r2[0] += mz[j] * bzv[j]; r2[1] += mr[j] * brv[j]; r2[2] += mh[j] * bhv[j];
        r2[3] += bzv[j] * bzv[j]; r2[4] += brv[j] * brv[j]; r2[5] += bhv[j] * bhv[j];
    }
    breduce(r2, sm, tid);

    MA Azc = madd(mz2, r2[3], r2[0]);
    MA Arc = madd(mr2, r2[4], r2[1]);
    MA Ahc = madd(mh2, r2[5], r2[2]);
    float Bz[4], Br[4], Bh[4];
    #pragma unroll
    for (int j = 0; j < 4; j++) {
        Bz[j] = Azc.a * mz[j] + Azc.b * bzv[j];
        Br[j] = Arc.a * mr[j] + Arc.b * brv[j];
        Bh[j] = Ahc.a * mh[j] + Ahc.b * bhv[j];
    }
    const float Bz2 = Azc.n2, Br2 = Arc.n2, Bh2 = Ahc.n2;

    float r3[2]; r3[0] = r3[1] = 0.f;
    #pragma unroll
    for (int j = 0; j < 4; j++) { r3[0] += az[j] * Bz[j]; r3[1] += arr[j] * Br[j]; }
    breduce(r3, sm, tid);

    float zv[4], rv[4];
    {
        MA U = madd(az2, Bz2, r3[0]);
        float n = sqrtf(fmaxf(U.n2, 1e-15f));
        float L = __fdividef(artanh_c(n), n);
        #pragma unroll
        for (int j = 0; j < 4; j++) {
            float u = U.a * az[j] + U.b * Bz[j];
            zv[j] = sigmoid_fast(L * u);
        }
        U = madd(ar2, Br2, r3[1]);
        n = sqrtf(fmaxf(U.n2, 1e-15f));
        L = __fdividef(artanh_c(n), n);
        #pragma unroll
        for (int j = 0; j < 4; j++) {
            float u = U.a * arr[j] + U.b * Br[j];
            rv[j] = sigmoid_fast(L * u);
        }
    }

    float rb[4];
    float r4[1]; r4[0] = 0.f;
    #pragma unroll
    for (int j = 0; j < 4; j++) { rb[j] = rv[j] * Bh[j]; r4[0] += rb[j] * rb[j]; }
    breduce(r4, sm, tid);
    float P[4], P2;
    {
        float Bhn = sqrtf(fmaxf(Bh2, 1e-15f));
        float q = __fdividef(artanh_c(Bhn), Bhn);
        float un = sqrtf(fmaxf(r4[0], 1e-15f));
        float t = tanh_fast(un * q);
        float f = __fdividef(t, un);
        P2 = t * t;
        #pragma unroll
        for (int j = 0; j < 4; j++) P[j] = f * rb[j];
    }

    float r5[1]; r5[0] = 0.f;
    #pragma unroll
    for (int j = 0; j < 4; j++) r5[0] += P[j] * ah[j];
    breduce(r5, sm, tid);
    MA Tc = madd(P2, ah2, r5[0]);
    float Tv[4];
    #pragma unroll
    for (int j = 0; j < 4; j++) Tv[j] = Tc.a * P[j] + Tc.b * ah[j];
    const float T2 = Tc.n2;

    float r6[1]; r6[0] = 0.f;
    #pragma unroll
    for (int j = 0; j < 4; j++) r6[0] += hv[j] * Tv[j];
    breduce(r6, sm, tid);
    MA Mc = madd(hs2, T2, -r6[0]);
    float Mv[4];
    #pragma unroll
    for (int j = 0; j < 4; j++) Mv[j] = -Mc.a * hv[j] + Mc.b * Tv[j];
    const float M2 = Mc.n2;

    float zM[4];
    float r7[1]; r7[0] = 0.f;
    #pragma unroll
    for (int j = 0; j < 4; j++) { zM[j] = zv[j] * Mv[j]; r7[0] += zM[j] * zM[j]; }
    breduce(r7, sm, tid);
    float Q[4], Q2;
    {
        float Mn = sqrtf(fmaxf(M2, 1e-15f));
        float q = __fdividef(artanh_c(Mn), Mn);
        float un = sqrtf(fmaxf(r7[0], 1e-15f));
        float t = tanh_fast(un * q);
        float f = __fdividef(t, un);
        Q2 = t * t;
        #pragma unroll
        for (int j = 0; j < 4; j++) Q[j] = f * zM[j];
    }

    float r8[1]; r8[0] = 0.f;
    #pragma unroll
    for (int j = 0; j < 4; j++) r8[0] += hv[j] * Q[j];
    breduce(r8, sm, tid);
    MA Fc = madd(hs2, Q2, r8[0]);
    float4 o;
    o.x = Fc.a * hv[0] + Fc.b * Q[0];
    o.y = Fc.a * hv[1] + Fc.b * Q[1];
    o.z = Fc.a * hv[2] + Fc.b * Q[2];
    o.w = Fc.a * hv[3] + Fc.b * Q[3];
    *(float4*)&out[rowoff] = o;
}

// ---------------------------------------------------------------------------
// Launch
// ---------------------------------------------------------------------------
extern "C" void kernel_launch(void* const* d_in, const int* in_sizes, int n_in,
                              void* d_out, int out_size)
{
    const float* inp   = (const float*)d_in[0];
    const float* ph    = (const float*)d_in[1];
    const float* w_iz  = (const float*)d_in[2];
    const float* w_hz  = (const float*)d_in[3];
    const float* b_z   = (const float*)d_in[4];
    const float* w_ir  = (const float*)d_in[5];
    const float* w_hr  = (const float*)d_in[6];
    const float* b_r   = (const float*)d_in[7];
    const float* w_ih  = (const float*)d_in[8];
    const float* w_hh  = (const float*)d_in[9];
    const float* b_h   = (const float*)d_in[10];
    float* out = (float*)d_out;

    asplit<<<dim3(BDIM * DDIM / 4 / 256, 2), 256>>>(inp, ph);
    wsplit<<<dim3(32, 32, 6), 256>>>(w_iz, w_hz, w_ir, w_hr, w_ih, w_hh);
    gemm_mma<<<dim3(HDIM / 128, BDIM / 128, 6), 256>>>();
    hyper_fuse<<<BDIM, 256>>>(inp, ph, b_z, b_r, b_h, out);
}